// round 4
// baseline (speedup 1.0000x reference)
#include <cuda_runtime.h>
#include <cuda_bf16.h>
#include <mma.h>

using namespace nvcuda;

#define Bb 16
#define Nn 4096
#define Dd 64

// Scratch (device globals; allocation in kernel_launch is forbidden)
__device__ __nv_bfloat16 g_Wb[(size_t)Nn * Nn];        // W, bf16, diagonal = 0
__device__ __nv_bfloat16 g_Xb[(size_t)Bb * Dd * Nn];   // X^T per (b,d): [c=b*64+d][j]
__device__ float         g_P [(size_t)Bb * Nn * Dd];   // X @ r_proj, fp32
__device__ float         g_l1[Nn];
__device__ float         g_l2[Nn];

// ---------------------------------------------------------------------------
// Kernel A: threshold incidence_m, scatter (skip diag), write incidence_all
// (fp32, diag=1) into d_out, bf16 W (diag=0) into scratch, per-row l1/l2.
// ---------------------------------------------------------------------------
__global__ void prep_kernel(const float* __restrict__ inc,
                            float* __restrict__ inc_all) {
    int i   = blockIdx.x;
    int tid = threadIdx.x;
    const float*   row  = inc     + (size_t)i * (Nn - 1);
    float*         orow = inc_all + (size_t)i * Nn;
    __nv_bfloat16* wrow = g_Wb    + (size_t)i * Nn;

    float mx = 0.f, ss = 0.f;
    for (int j = tid; j < Nn - 1; j += 256) {
        float x = row[j];
        float v = (x > 0.01f) ? x : 0.f;       // w >= 0 always
        int col = j + (j >= i ? 1 : 0);
        orow[col] = v;
        wrow[col] = __float2bfloat16(v);
        mx = fmaxf(mx, v);
        ss += v * v;
    }
    if (tid == 0) {
        orow[i] = 1.f;                          // incidence_all diagonal
        wrow[i] = __float2bfloat16(0.f);        // W diagonal stays zero
    }

    __shared__ float smx[256], sss[256];
    smx[tid] = mx; sss[tid] = ss;
    __syncthreads();
    for (int s = 128; s > 0; s >>= 1) {
        if (tid < s) {
            smx[tid] = fmaxf(smx[tid], smx[tid + s]);
            sss[tid] += sss[tid + s];
        }
        __syncthreads();
    }
    if (tid == 0) {
        g_l1[i] = smx[0];
        g_l2[i] = sqrtf(sss[0]);
    }
}

// ---------------------------------------------------------------------------
// Kernel B: X_proj = X @ r_proj (fp32) and bf16 transpose of X into g_Xb.
// One block = 32 consecutive rows of X (all inside one batch since 4096%32==0).
// ---------------------------------------------------------------------------
__global__ void proj_kernel(const float* __restrict__ X,
                            const float* __restrict__ rp) {
    __shared__ float Rs[64 * 64];
    __shared__ float Xs[32][65];                // padded: conflict-free transpose
    int tid = threadIdx.x;
    int r0  = blockIdx.x * 32;                  // global flattened row (b*N+i)

    for (int t = tid; t < 4096; t += 256) Rs[t] = rp[t];
    #pragma unroll
    for (int t = 0; t < 8; t++) {
        int e = tid + t * 256;
        Xs[e >> 6][e & 63] = X[(size_t)(r0 + (e >> 6)) * 64 + (e & 63)];
    }
    __syncthreads();

    // P = X @ r_proj
    #pragma unroll
    for (int t = 0; t < 8; t++) {
        int e = tid + t * 256;
        int row = e >> 6, d = e & 63;
        float acc = 0.f;
        #pragma unroll
        for (int k = 0; k < 64; k++) acc += Xs[row][k] * Rs[k * 64 + d];
        g_P[(size_t)(r0 + row) * 64 + d] = acc;
    }

    // bf16 transpose: g_Xb[(b*64+d)][i] = X[b,i,d]
    int b  = r0 >> 12;
    int ib = r0 & (Nn - 1);
    #pragma unroll
    for (int t = 0; t < 8; t++) {
        int e  = tid + t * 256;
        int il = e & 31, d = e >> 5;
        g_Xb[(size_t)(b * 64 + d) * Nn + ib + il] = __float2bfloat16(Xs[il][d]);
    }
}

// ---------------------------------------------------------------------------
// Kernel C: recon = W @ X (bf16 WMMA, fp32 accum), fused loss epilogue.
// Block tile: 128 rows (i) x 64 cols (= one batch's full D) x K=32 chunks.
// 8 warps: 4 along M x 2 along N, each warp 32x32 via 2x2 wmma frags.
// ---------------------------------------------------------------------------
#define KC  32
#define LDA 40   // bf16 stride for A/B smem tiles (16B aligned, conflict-spread)
#define LDR 72   // fp32 stride for recon epilogue tile

__global__ __launch_bounds__(256)
void gemm_loss_kernel(float* __restrict__ out) {
    __shared__ __align__(16) unsigned char smem[128 * LDR * 4];  // 36.9 KB union
    __nv_bfloat16* As = (__nv_bfloat16*)smem;       // [128][LDA]
    __nv_bfloat16* Bs = As + 128 * LDA;             // [64][LDA]
    float*         Rs = (float*)smem;               // [128][LDR] (after mainloop)

    int tid  = threadIdx.x;
    int warp = tid >> 5;
    int wm   = warp & 3;        // 0..3 along M
    int wn   = warp >> 2;       // 0..1 along N
    int i0   = blockIdx.x * 128;
    int ct   = blockIdx.y;      // batch index

    wmma::fragment<wmma::accumulator, 16, 16, 16, float> acc[2][2];
    #pragma unroll
    for (int mi = 0; mi < 2; mi++)
        #pragma unroll
        for (int ni = 0; ni < 2; ni++) wmma::fill_fragment(acc[mi][ni], 0.f);

    const __nv_bfloat16* Ag = g_Wb + (size_t)i0 * Nn;
    const __nv_bfloat16* Bg = g_Xb + (size_t)ct * 64 * Nn;

    // register prefetch addressing (uint4 = 8 bf16)
    int ra0 = (tid) >> 2,       ka0 = (tid & 3) * 8;
    int ra1 = (tid + 256) >> 2, ka1 = ka0;
    int rb  = tid >> 2,         kb  = (tid & 3) * 8;

    uint4 pa0, pa1, pb;
    // preload kt = 0
    pa0 = *(const uint4*)(Ag + (size_t)ra0 * Nn + ka0);
    pa1 = *(const uint4*)(Ag + (size_t)ra1 * Nn + ka1);
    pb  = *(const uint4*)(Bg + (size_t)rb  * Nn + kb);

    for (int kt = 0; kt < Nn; kt += KC) {
        *(uint4*)(As + ra0 * LDA + ka0) = pa0;
        *(uint4*)(As + ra1 * LDA + ka1) = pa1;
        *(uint4*)(Bs + rb  * LDA + kb)  = pb;
        __syncthreads();

        int ktn = kt + KC;
        if (ktn < Nn) {   // prefetch next tile; latency hidden by MMA below
            pa0 = *(const uint4*)(Ag + (size_t)ra0 * Nn + ktn + ka0);
            pa1 = *(const uint4*)(Ag + (size_t)ra1 * Nn + ktn + ka1);
            pb  = *(const uint4*)(Bg + (size_t)rb  * Nn + ktn + kb);
        }

        #pragma unroll
        for (int kk = 0; kk < KC; kk += 16) {
            wmma::fragment<wmma::matrix_a, 16, 16, 16, __nv_bfloat16, wmma::row_major> a0, a1;
            wmma::fragment<wmma::matrix_b, 16, 16, 16, __nv_bfloat16, wmma::col_major> b0, b1;
            wmma::load_matrix_sync(a0, As + (wm * 32)      * LDA + kk, LDA);
            wmma::load_matrix_sync(a1, As + (wm * 32 + 16) * LDA + kk, LDA);
            wmma::load_matrix_sync(b0, Bs + (wn * 32)      * LDA + kk, LDA);
            wmma::load_matrix_sync(b1, Bs + (wn * 32 + 16) * LDA + kk, LDA);
            wmma::mma_sync(acc[0][0], a0, b0, acc[0][0]);
            wmma::mma_sync(acc[0][1], a0, b1, acc[0][1]);
            wmma::mma_sync(acc[1][0], a1, b0, acc[1][0]);
            wmma::mma_sync(acc[1][1], a1, b1, acc[1][1]);
        }
        __syncthreads();
    }

    // Epilogue: recon tile -> smem, then per-row loss reduction
    #pragma unroll
    for (int mi = 0; mi < 2; mi++)
        #pragma unroll
        for (int ni = 0; ni < 2; ni++)
            wmma::store_matrix_sync(Rs + (wm * 32 + mi * 16) * LDR + wn * 32 + ni * 16,
                                    acc[mi][ni], LDR, wmma::mem_row_major);
    __syncthreads();

    int row  = tid >> 1;
    int half = tid & 1;
    const float* Prow = g_P + ((size_t)ct * Nn + i0 + row) * 64;
    float s = 0.f;
    #pragma unroll
    for (int k = 0; k < 32; k++) {
        int d = half * 32 + k;
        float diff = Prow[d] - Rs[row * LDR + d];
        s += diff * diff;
    }
    s += __shfl_xor_sync(0xffffffffu, s, 1);
    if (half == 0) {
        int i = i0 + row;
        out[ct * Nn + i] = 0.2f * sqrtf(s) + g_l1[i] + 0.001f * g_l2[i];
    }
}

// ---------------------------------------------------------------------------
extern "C" void kernel_launch(void* const* d_in, const int* in_sizes, int n_in,
                              void* d_out, int out_size) {
    const float* X   = (const float*)d_in[0];   // [16,4096,64]
    const float* rp  = (const float*)d_in[1];   // [64,64]
    const float* inc = (const float*)d_in[2];   // [4096,4095]
    float* out     = (float*)d_out;             // loss [16,4096]
    float* inc_all = out + (size_t)Bb * Nn;     // incidence_all [4096,4096]

    prep_kernel<<<Nn, 256>>>(inc, inc_all);
    proj_kernel<<<(Bb * Nn) / 32, 256>>>(X, rp);
    dim3 g(Nn / 128, Bb);
    gemm_loss_kernel<<<g, 256>>>(out);
}

// round 5
// speedup vs baseline: 1.4988x; 1.4988x over previous
#include <cuda_runtime.h>
#include <cuda_bf16.h>
#include <mma.h>

using namespace nvcuda;

#define Bb 16
#define Nn 4096
#define Dd 64

// Scratch (device globals; allocation in kernel_launch is forbidden)
__device__ __align__(16) __nv_bfloat16 g_Wb[(size_t)Nn * Nn];      // W bf16, diag=0
__device__ __align__(16) __nv_bfloat16 g_Xb[(size_t)Bb * Dd * Nn]; // X^T: [b*64+d][j]
__device__ __align__(16) float         g_P [(size_t)Bb * Nn * Dd]; // X @ r_proj
__device__ float g_l1[Nn];
__device__ float g_l2[Nn];

// ---------------------------------------------------------------------------
// Kernel A: threshold + diagonal-skip scatter, staged through smem so every
// global store is fully vectorized/aligned. Also computes per-row l1/l2.
// ---------------------------------------------------------------------------
__global__ __launch_bounds__(256)
void prep_kernel(const float* __restrict__ inc, float* __restrict__ inc_all) {
    __shared__ float srow[Nn];          // thresholded row, diag slot = 0
    __shared__ float smx[256], sss[256];
    int i   = blockIdx.x;
    int tid = threadIdx.x;
    const float* row = inc + (size_t)i * (Nn - 1);

    if (tid == 0) srow[i] = 0.f;
    float mx = 0.f, ss = 0.f;
    #pragma unroll 4
    for (int j = tid; j < Nn - 1; j += 256) {
        float x = __ldg(row + j);
        float v = (x > 0.01f) ? x : 0.f;
        srow[j + (j >= i ? 1 : 0)] = v;
        mx = fmaxf(mx, v);
        ss += v * v;
    }
    smx[tid] = mx; sss[tid] = ss;
    __syncthreads();

    // inc_all: aligned float4 stores, patch diagonal to 1.0 in-register
    float* orow = inc_all + (size_t)i * Nn;
    int iv = i >> 2;
    #pragma unroll
    for (int t = 0; t < 4; t++) {
        int c4 = tid + t * 256;                         // 0..1023
        float4 v = reinterpret_cast<const float4*>(srow)[c4];
        if (c4 == iv) reinterpret_cast<float*>(&v)[i & 3] = 1.f;
        reinterpret_cast<float4*>(orow)[c4] = v;
    }

    // W: aligned uint4 stores of 8 bf16 (diag stays 0)
    __nv_bfloat16* wrow = g_Wb + (size_t)i * Nn;
    #pragma unroll
    for (int t = 0; t < 2; t++) {
        int c8 = tid + t * 256;                         // 0..511
        const float* s8 = srow + c8 * 8;
        __nv_bfloat162 h0 = __floats2bfloat162_rn(s8[0], s8[1]);
        __nv_bfloat162 h1 = __floats2bfloat162_rn(s8[2], s8[3]);
        __nv_bfloat162 h2 = __floats2bfloat162_rn(s8[4], s8[5]);
        __nv_bfloat162 h3 = __floats2bfloat162_rn(s8[6], s8[7]);
        uint4 u;
        u.x = *reinterpret_cast<unsigned*>(&h0);
        u.y = *reinterpret_cast<unsigned*>(&h1);
        u.z = *reinterpret_cast<unsigned*>(&h2);
        u.w = *reinterpret_cast<unsigned*>(&h3);
        reinterpret_cast<uint4*>(wrow)[c8] = u;
    }

    for (int s = 128; s > 0; s >>= 1) {
        if (tid < s) {
            smx[tid] = fmaxf(smx[tid], smx[tid + s]);
            sss[tid] += sss[tid + s];
        }
        __syncthreads();
    }
    if (tid == 0) {
        g_l1[i] = smx[0];
        g_l2[i] = sqrtf(sss[0]);
    }
}

// ---------------------------------------------------------------------------
// Kernel B: X_proj = X @ r_proj (fp32) and bf16 transpose of X into g_Xb.
// ---------------------------------------------------------------------------
__global__ __launch_bounds__(256)
void proj_kernel(const float* __restrict__ X, const float* __restrict__ rp) {
    __shared__ float Rs[64 * 64];
    __shared__ float Xs[32][65];
    int tid = threadIdx.x;
    int r0  = blockIdx.x * 32;

    for (int t = tid; t < 4096; t += 256) Rs[t] = rp[t];
    #pragma unroll
    for (int t = 0; t < 8; t++) {
        int e = tid + t * 256;
        Xs[e >> 6][e & 63] = X[(size_t)(r0 + (e >> 6)) * 64 + (e & 63)];
    }
    __syncthreads();

    #pragma unroll
    for (int t = 0; t < 8; t++) {
        int e = tid + t * 256;
        int row = e >> 6, d = e & 63;
        float acc = 0.f;
        #pragma unroll
        for (int k = 0; k < 64; k++) acc += Xs[row][k] * Rs[k * 64 + d];
        g_P[(size_t)(r0 + row) * 64 + d] = acc;
    }

    int b  = r0 >> 12;
    int ib = r0 & (Nn - 1);
    #pragma unroll
    for (int t = 0; t < 8; t++) {
        int e  = tid + t * 256;
        int il = e & 31, d = e >> 5;
        g_Xb[(size_t)(b * 64 + d) * Nn + ib + il] = __float2bfloat16(Xs[il][d]);
    }
}

// ---------------------------------------------------------------------------
// Kernel C: recon = W @ X (bf16 WMMA), 128x256x64 tiles, cp.async double
// buffer, fused loss epilogue over 4 batches per block.
// ---------------------------------------------------------------------------
#define MT  128
#define NT  256
#define KC  64
#define LDA 72         // bf16 smem stride (16B aligned, pad 8)
#define LDR 132        // fp32 epilogue stride
#define STAGES (Nn / KC)
#define BUFELEMS ((MT + NT) * LDA)   // 27648 bf16 per buffer

__device__ __forceinline__ void cp16(void* s, const void* g) {
    unsigned sa = (unsigned)__cvta_generic_to_shared(s);
    asm volatile("cp.async.cg.shared.global [%0], [%1], 16;" :: "r"(sa), "l"(g));
}

extern __shared__ unsigned char dynsmem[];

__global__ __launch_bounds__(512, 1)
void gemm_loss_kernel(float* __restrict__ out) {
    __nv_bfloat16* sm = reinterpret_cast<__nv_bfloat16*>(dynsmem);

    int tid  = threadIdx.x;
    int warp = tid >> 5;
    int wm   = warp & 3;          // 4 warps along M (32 rows each)
    int wn   = warp >> 2;         // 4 warps along N (64 cols each)
    int i0   = blockIdx.x * MT;
    int c0   = blockIdx.y * NT;

    const __nv_bfloat16* Ag = g_Wb + (size_t)i0 * Nn;
    const __nv_bfloat16* Bg = g_Xb + (size_t)c0 * Nn;

    wmma::fragment<wmma::accumulator, 16, 16, 16, float> acc[2][4];
    #pragma unroll
    for (int mi = 0; mi < 2; mi++)
        #pragma unroll
        for (int ni = 0; ni < 4; ni++) wmma::fill_fragment(acc[mi][ni], 0.f);

    // ---- stage loader: A tile 128x64 (1024 x 16B), B tile 256x64 (2048 x 16B)
    auto load_stage = [&](int kt, int buf) {
        __nv_bfloat16* As = sm + buf * BUFELEMS;
        __nv_bfloat16* Bs = As + MT * LDA;
        #pragma unroll
        for (int t = 0; t < 2; t++) {
            int idx = tid + t * 512;
            int r = idx >> 3, c = (idx & 7) * 8;
            cp16(As + r * LDA + c, Ag + (size_t)r * Nn + kt + c);
        }
        #pragma unroll
        for (int t = 0; t < 4; t++) {
            int idx = tid + t * 512;
            int r = idx >> 3, c = (idx & 7) * 8;
            cp16(Bs + r * LDA + c, Bg + (size_t)r * Nn + kt + c);
        }
    };

    load_stage(0, 0);
    asm volatile("cp.async.commit_group;");

    #pragma unroll 1
    for (int s = 0; s < STAGES; s++) {
        if (s + 1 < STAGES) {
            load_stage((s + 1) * KC, (s + 1) & 1);
            asm volatile("cp.async.commit_group;");
            asm volatile("cp.async.wait_group 1;");
        } else {
            asm volatile("cp.async.wait_group 0;");
        }
        __syncthreads();

        const __nv_bfloat16* As = sm + (s & 1) * BUFELEMS;
        const __nv_bfloat16* Bs = As + MT * LDA;
        #pragma unroll
        for (int kk = 0; kk < KC; kk += 16) {
            wmma::fragment<wmma::matrix_a, 16, 16, 16, __nv_bfloat16, wmma::row_major> a[2];
            wmma::fragment<wmma::matrix_b, 16, 16, 16, __nv_bfloat16, wmma::col_major> b[4];
            #pragma unroll
            for (int mi = 0; mi < 2; mi++)
                wmma::load_matrix_sync(a[mi], As + (wm * 32 + mi * 16) * LDA + kk, LDA);
            #pragma unroll
            for (int ni = 0; ni < 4; ni++)
                wmma::load_matrix_sync(b[ni], Bs + (wn * 64 + ni * 16) * LDA + kk, LDA);
            #pragma unroll
            for (int mi = 0; mi < 2; mi++)
                #pragma unroll
                for (int ni = 0; ni < 4; ni++)
                    wmma::mma_sync(acc[mi][ni], a[mi], b[ni], acc[mi][ni]);
        }
        __syncthreads();
    }

    // ---- Epilogue: two 128-col phases (2 batches each), reduce in-block
    float* Rs = reinterpret_cast<float*>(dynsmem);   // [128][LDR]
    #pragma unroll
    for (int p = 0; p < 2; p++) {
        if ((wn >> 1) == p) {
            int wcol = (wn & 1) * 64;
            #pragma unroll
            for (int mi = 0; mi < 2; mi++)
                #pragma unroll
                for (int ni = 0; ni < 4; ni++)
                    wmma::store_matrix_sync(
                        Rs + (wm * 32 + mi * 16) * LDR + wcol + ni * 16,
                        acc[mi][ni], LDR, wmma::mem_row_major);
        }
        __syncthreads();

        int pair = tid >> 1, half = tid & 1;
        int row  = pair & 127;
        int ctl  = pair >> 7;                       // 0..1
        int ct   = blockIdx.y * 4 + p * 2 + ctl;
        int i    = i0 + row;
        const float* Prow = g_P + ((size_t)ct * Nn + i) * 64;
        float sum = 0.f;
        #pragma unroll
        for (int k = 0; k < 32; k++) {
            int d = half * 32 + k;
            float diff = Prow[d] - Rs[row * LDR + ctl * 64 + d];
            sum += diff * diff;
        }
        sum += __shfl_xor_sync(0xffffffffu, sum, 1);
        if (half == 0)
            out[ct * Nn + i] = 0.2f * sqrtf(sum) + g_l1[i] + 0.001f * g_l2[i];
        __syncthreads();
    }
}

// ---------------------------------------------------------------------------
extern "C" void kernel_launch(void* const* d_in, const int* in_sizes, int n_in,
                              void* d_out, int out_size) {
    const float* X   = (const float*)d_in[0];   // [16,4096,64]
    const float* rp  = (const float*)d_in[1];   // [64,64]
    const float* inc = (const float*)d_in[2];   // [4096,4095]
    float* out     = (float*)d_out;             // loss [16,4096]
    float* inc_all = out + (size_t)Bb * Nn;     // incidence_all [4096,4096]

    static_assert(2 * BUFELEMS * 2 >= MT * LDR * 4, "epilogue fits");
    const int smem_bytes = 2 * BUFELEMS * 2;    // 110592
    cudaFuncSetAttribute(gemm_loss_kernel,
                         cudaFuncAttributeMaxDynamicSharedMemorySize, smem_bytes);

    prep_kernel<<<Nn, 256>>>(inc, inc_all);
    proj_kernel<<<(Bb * Nn) / 32, 256>>>(X, rp);
    dim3 g(Nn / MT, (Bb * Dd) / NT);            // (32, 4)
    gemm_loss_kernel<<<g, 512, smem_bytes>>>(out);
}